// round 15
// baseline (speedup 1.0000x reference)
#include <cuda_runtime.h>
#include <cuda_bf16.h>
#include <math.h>
#include <math_constants.h>

#define Bn 16
#define Gn 32
#define Nn 8400
#define NCc 80
#define BINSc 16
#define CH 144          // 4*BINS + NC
#define EPSf 1e-9f
#define MAXFG (Bn * Gn * 10)   // 5120
#define NROWS (Bn * Gn)        // 512

#define PRED_BLOCKS 525        // 525*256 == Bn*Nn exactly
#define ASSIGN_BLOCKS 64
#define F0_BLOCKS 1170         // level-0 focal sweep (p0)
#define F1_BLOCKS 293          // level-1 focal sweep (p1)
#define F2_BLOCKS 73           // level-2 focal sweep (p2)
#define ASSIGN_BASE PRED_BLOCKS                      // 525
#define F0_BASE (ASSIGN_BASE + ASSIGN_BLOCKS)        // 589
#define F1_BASE (F0_BASE + F0_BLOCKS)                // 1759
#define F2_BASE (F1_BASE + F1_BLOCKS)                // 2052
#define K_BLOCKS (F2_BASE + F2_BLOCKS)               // 2125

// ---------------- scratch (device globals; zero-init at load) ----------------
__device__ float4 g_pred[Bn * Nn];            // pred boxes (x1,y1,x2,y2)
__device__ float4 g_lse[Bn * Nn];             // per-side logsumexp of dfl logits
__device__ unsigned int g_bits[Bn * Nn];      // per-anchor gt bitmask
__device__ int    g_claim[Bn * Nn];           // dedup flag (self-cleaning)
__device__ int    g_topn[NROWS * 10];         // per-row selected anchor indices
__device__ int    g_topcnt[NROWS];
__device__ int    g_ovmax_i[NROWS];           // float-as-int maxima; reset by finisher
__device__ int    g_almax_i[NROWS];
__device__ int    g_fglist[MAXFG];            // t*32 + matched_g
__device__ int    g_cnt;                      // fg count; reset by finisher
__device__ int    g_done;                     // completion counter; reset by finisher
__device__ int    g_bar;                      // grid barrier counter; reset by finisher
__device__ int    g_predready;                // pred-block completion; reset by finisher
__device__ double g_acc[3];                   // ciou, dfl, focal-corr; reset by finisher
__device__ double g_focal;                    // dense focal base; reset by finisher

__constant__ int   c_base[3]   = { 0, 6400, 8000 };
__constant__ int   c_W[3]      = { 80, 40, 20 };
__constant__ float c_stride[3] = { 8.f, 16.f, 32.f };

// ---------------- helpers ----------------
__device__ __forceinline__ void decode_anchor(int n, const float*& p,
    const float* p0, const float* p1, const float* p2,
    int& hw, int& W, int& HW, float& stride)
{
    if (n < 6400)      { p = p0; hw = n;        W = 80; HW = 6400; stride = 8.f;  }
    else if (n < 8000) { p = p1; hw = n - 6400; W = 40; HW = 1600; stride = 16.f; }
    else               { p = p2; hw = n - 8000; W = 20; HW = 400;  stride = 32.f; }
}

__device__ __forceinline__ float iou_fn(float4 pb, float gx1, float gy1,
                                        float gx2, float gy2)
{
    float iw = fmaxf(fminf(gx2, pb.z) - fmaxf(gx1, pb.x), 0.f);
    float ih = fmaxf(fminf(gy2, pb.w) - fmaxf(gy1, pb.y), 0.f);
    float inter = iw * ih;
    float ag = (gx2 - gx1) * (gy2 - gy1);
    float ap = fmaxf(pb.z - pb.x, 0.f) * fmaxf(pb.w - pb.y, 0.f);
    return inter / (ag + ap - inter + EPSf);
}

__device__ __forceinline__ float align_fn(float iou, float l)
{
    float sc = 1.f / (1.f + expf(-l));
    float i2 = iou * iou;
    return sqrtf(sc) * i2 * i2 * i2;
}

__device__ __forceinline__ float focal_base(float l)   // precise (per-anchor path)
{
    float E = expf(l);
    float r = 1.f / (1.f + E);
    float pr = E * r;
    float sp = log1pf(E);
    return 0.75f * pr * pr * sp;
}

__device__ __forceinline__ float focal_base_fast(float l)  // dense-sweep path
{
    // 0.75 * sigmoid(l)^2 * softplus(l), all-MUFU approx path:
    // E = e^l; pr = E/(1+E) (approx rcp); sp = lg2(1+E)*ln2 (fold ln2 into const)
    float E = __expf(l);                 // logits ~N(0,1): no overflow
    float u = 1.f + E;
    float pr = __fdividef(E, u);         // FMUL * MUFU.RCP
    float l2u = __log2f(u);              // MUFU.LG2
    return (0.75f * 0.6931471805599453f) * pr * pr * l2u;
}

// level-specialized focal sweep: compile-time HW -> constant-divisor index math,
// fp32 per-thread accumulation (small term count), one double convert at end
template<int HW>
__device__ __forceinline__ double focal_level(const float* __restrict__ p,
                                              int start, int nthreads)
{
    const int per = NCc * HW / 4;        // compile-time constant
    const int TOT = Bn * per;
    float fsum = 0.f;
    for (int t4 = start; t4 < TOT; t4 += nthreads) {
        int b = t4 / per;                // constant division -> mul/shift
        int r = t4 - b * per;
        const float4* base = (const float4*)(p + ((size_t)b * CH + 4 * BINSc) * HW);
        float4 x = base[r];
        fsum += (focal_base_fast(x.x) + focal_base_fast(x.y)) +
                (focal_base_fast(x.z) + focal_base_fast(x.w));
    }
    return (double)fsum;
}

__device__ __forceinline__ double blkReduce256(double v)
{
    __shared__ double sh[8];
    int lane = threadIdx.x & 31, w = threadIdx.x >> 5;
    #pragma unroll
    for (int o = 16; o; o >>= 1) v += __shfl_down_sync(0xffffffffu, v, o);
    if (lane == 0) sh[w] = v;
    __syncthreads();
    v = (threadIdx.x < 8) ? sh[threadIdx.x] : 0.0;
    if (w == 0) {
        #pragma unroll
        for (int o = 4; o; o >>= 1) v += __shfl_down_sync(0xffu, v, o);
    }
    __syncthreads();
    return v;
}

// software grid barrier among the ASSIGN blocks only
__device__ __forceinline__ void grid_barrier(int target)
{
    __syncthreads();
    if (threadIdx.x == 0) {
        __threadfence();
        atomicAdd(&g_bar, 1);
        while (atomicAdd(&g_bar, 0) < target) __nanosleep(32);
    }
    __syncthreads();
}

// ---------------- THE kernel: pred + assign + focal, one launch ----------------
__global__ void __launch_bounds__(256, 6)
k_all(const float* __restrict__ p0, const float* __restrict__ p1,
      const float* __restrict__ p2,
      const float* __restrict__ gtb, const int* __restrict__ gtl,
      float* __restrict__ out)
{
    const int tid = threadIdx.x;
    const int bid = blockIdx.x;

    if (bid < PRED_BLOCKS) {
        // ================= pred/DFL blocks =================
        int t = bid * 256 + tid;                     // exactly Bn*Nn threads
        g_bits[t] = 0u;
        int b = t / Nn, n = t % Nn;
        const float* p; int hw, W, HW; float stride;
        decode_anchor(n, p, p0, p1, p2, hw, W, HW, stride);
        const float* base = p + ((size_t)b * CH) * HW + hw;
        float cx = ((hw % W) + 0.5f) * stride;
        float cy = ((hw / W) + 0.5f) * stride;
        float dist[4], lse[4];
        #pragma unroll
        for (int s = 0; s < 4; s++) {
            float l[BINSc], m = -1e30f;
            #pragma unroll
            for (int j = 0; j < BINSc; j++) {
                l[j] = base[(size_t)(s * BINSc + j) * HW];
                m = fmaxf(m, l[j]);
            }
            float sum = 0.f, ws = 0.f;
            #pragma unroll
            for (int j = 0; j < BINSc; j++) {
                float e = expf(l[j] - m);
                sum += e; ws += (float)j * e;
            }
            dist[s] = ws / sum * stride;
            lse[s] = m + logf(sum);
        }
        g_pred[t] = make_float4(cx - dist[0], cy - dist[1], cx + dist[2], cy + dist[3]);
        g_lse[t]  = make_float4(lse[0], lse[1], lse[2], lse[3]);
        // release: this block's pred data visible before counter bump
        __syncthreads();
        __threadfence();
        if (tid == 0) atomicAdd(&g_predready, 1);
    } else if (bid < F0_BASE) {
        // ================= assign blocks =================
        // wait for ALL pred blocks (acquire)
        if (tid == 0) {
            while (atomicAdd(&g_predready, 0) < PRED_BLOCKS) __nanosleep(64);
        }
        __syncthreads();
        __threadfence();

        const int abid = bid - ASSIGN_BASE;          // 0..63
        const int gtid = abid * 256 + tid;

        // ---------- phase 1: top-k (warp per row) ----------
        {
            const int row = gtid >> 5;               // 0..511 exactly
            const int lane = tid & 31;
            const int b = row >> 5, g = row & 31;
            const float gx1 = gtb[row * 4 + 0], gy1 = gtb[row * 4 + 1];
            const float gx2 = gtb[row * 4 + 2], gy2 = gtb[row * 4 + 3];
            const int lab = gtl[row];
            const float* const pp[3] = { p0, p1, p2 };

            int jx0[3], nx[3], jy0[3], pre[4];
            pre[0] = 0;
            #pragma unroll
            for (int l = 0; l < 3; l++) {
                float s = c_stride[l]; int W = c_W[l];
                int x0 = max(0, (int)floorf(gx1 / s - 0.5f));
                int x1 = min(W - 1, (int)ceilf (gx2 / s - 0.5f));
                int y0 = max(0, (int)floorf(gy1 / s - 0.5f));
                int y1 = min(W - 1, (int)ceilf (gy2 / s - 0.5f));
                jx0[l] = x0; nx[l] = max(0, x1 - x0 + 1);
                jy0[l] = y0; int nyl = max(0, y1 - y0 + 1);
                pre[l + 1] = pre[l] + nx[l] * nyl;
            }
            const int total = pre[3];

            float val[10]; int idx[10];
            #pragma unroll
            for (int k = 0; k < 10; k++) { val[k] = 0.f; idx[k] = 0x7fffffff; }

            for (int c = lane; c < total; c += 32) {
                int l = (c >= pre[1]) + (c >= pre[2]);
                int e = c - pre[l];
                int iy = e / nx[l], ix = e - iy * nx[l];
                int j = jx0[l] + ix, i = jy0[l] + iy;
                float s = c_stride[l];
                float cx = (j + 0.5f) * s;
                float cy = (i + 0.5f) * s;
                if (!(cx > gx1 && cx < gx2 && cy > gy1 && cy < gy2)) continue;
                int W = c_W[l], HW = W * W;
                int hw = i * W + j;
                int n = c_base[l] + hw;
                float4 pb = g_pred[b * Nn + n];
                float iou = iou_fn(pb, gx1, gy1, gx2, gy2);
                float lg = pp[l][((size_t)b * CH + 4 * BINSc + lab) * HW + hw];
                float al = align_fn(iou, lg);
                if (al <= EPSf) continue;
                if (al > val[9] || (al == val[9] && n < idx[9])) {
                    val[9] = al; idx[9] = n;
                    #pragma unroll
                    for (int k = 9; k >= 1; k--) {
                        if (val[k] > val[k - 1] ||
                            (val[k] == val[k - 1] && idx[k] < idx[k - 1])) {
                            float tv = val[k]; val[k] = val[k - 1]; val[k - 1] = tv;
                            int ti = idx[k]; idx[k] = idx[k - 1]; idx[k - 1] = ti;
                        }
                    }
                }
            }

            int cnt = 0;
            for (int it = 0; it < 10; it++) {
                unsigned long long pack =
                    ((unsigned long long)(unsigned)__float_as_int(val[0]) << 32) |
                    (unsigned)(~(unsigned)idx[0]);
                #pragma unroll
                for (int o = 16; o; o >>= 1) {
                    unsigned long long other = __shfl_xor_sync(0xffffffffu, pack, o);
                    if (other > pack) pack = other;
                }
                float wv = __int_as_float((int)(pack >> 32));
                if (wv <= EPSf) break;
                int wn = (int)(~(unsigned)pack);
                if (lane == 0) {
                    g_topn[row * 10 + it] = wn;
                    atomicOr(&g_bits[b * Nn + wn], 1u << g);
                }
                cnt++;
                if (idx[0] == wn) {
                    #pragma unroll
                    for (int k = 0; k < 9; k++) { val[k] = val[k + 1]; idx[k] = idx[k + 1]; }
                    val[9] = 0.f; idx[9] = 0x7fffffff;
                }
            }
            if (lane == 0) g_topcnt[row] = cnt;
        }

        grid_barrier(ASSIGN_BLOCKS);              // g_bar reaches 64

        // ---------- phase 2: resolve ----------
        if (gtid < NROWS * 10) {
            int row = gtid / 10, slot = gtid % 10;
            if (slot < __ldcg(&g_topcnt[row])) {
                int b = row >> 5;
                int n = __ldcg(&g_topn[row * 10 + slot]);
                int t = b * Nn + n;
                if (!atomicExch(&g_claim[t], 1)) {
                    unsigned int bits = __ldcg(&g_bits[t]);
                    float4 pb = g_pred[t];
                    int mg;
                    if (__popc(bits) > 1) {
                        const float* gbase = gtb + (size_t)b * Gn * 4;
                        float bo = -1.f; int bg = 0;
                        #pragma unroll 8
                        for (int g = 0; g < Gn; g++) {
                            float iou = iou_fn(pb, gbase[g * 4 + 0], gbase[g * 4 + 1],
                                               gbase[g * 4 + 2], gbase[g * 4 + 3]);
                            if (iou > bo) { bo = iou; bg = g; }
                        }
                        mg = bg;
                    } else {
                        mg = __ffs(bits) - 1;
                    }
                    int pos = atomicAdd(&g_cnt, 1);
                    g_fglist[pos] = t * 32 + mg;
                    const float* gb = gtb + ((size_t)(b * Gn + mg)) * 4;
                    int lab = gtl[b * Gn + mg];
                    const float* p; int hw, W, HW; float stride;
                    decode_anchor(n, p, p0, p1, p2, hw, W, HW, stride);
                    float iou = iou_fn(pb, gb[0], gb[1], gb[2], gb[3]);
                    float l = p[((size_t)b * CH + 4 * BINSc + lab) * HW + hw];
                    float al = align_fn(iou, l);
                    atomicMax(&g_ovmax_i[b * Gn + mg], __float_as_int(iou));
                    atomicMax(&g_almax_i[b * Gn + mg], __float_as_int(al));
                }
            }
        }

        grid_barrier(2 * ASSIGN_BLOCKS);          // g_bar reaches 128

        // ---------- phase 3: per-fg losses ----------
        __shared__ int s_cnt;
        if (tid == 0) s_cnt = atomicAdd(&g_cnt, 0);
        __syncthreads();
        const int cnt = s_cnt;

        double aciou = 0.0, adfl = 0.0, acorr = 0.0;
        if (gtid < cnt) {
            int code = __ldcg(&g_fglist[gtid]);
            int t = code >> 5, mg = code & 31;
            g_claim[t] = 0;                       // self-clean
            int b = t / Nn, n = t % Nn;
            const float* p; int hw, W, HW; float stride;
            decode_anchor(n, p, p0, p1, p2, hw, W, HW, stride);
            float cx = ((hw % W) + 0.5f) * stride;
            float cy = ((hw / W) + 0.5f) * stride;
            const float* gb = gtb + ((size_t)(b * Gn + mg)) * 4;
            float tx1 = gb[0], ty1 = gb[1], tx2 = gb[2], ty2 = gb[3];
            int lab = gtl[b * Gn + mg];
            float4 pb = g_pred[t];
            // norm
            float iou0 = iou_fn(pb, tx1, ty1, tx2, ty2);
            float lcls = p[((size_t)b * CH + 4 * BINSc + lab) * HW + hw];
            float al = align_fn(iou0, lcls);
            float ovmax = __int_as_float(__ldcg(&g_ovmax_i[b * Gn + mg]));
            float almax = __int_as_float(__ldcg(&g_almax_i[b * Gn + mg]));
            float norm = fmaxf(al * ovmax / (almax + EPSf), 0.f);
            // CIoU
            float w1 = pb.z - pb.x, h1 = pb.w - pb.y;
            float w2 = tx2 - tx1,   h2 = ty2 - ty1;
            float iw = fmaxf(fminf(pb.z, tx2) - fmaxf(pb.x, tx1), 0.f);
            float ih = fmaxf(fminf(pb.w, ty2) - fmaxf(pb.y, ty1), 0.f);
            float inter = iw * ih;
            float uni = w1 * h1 + w2 * h2 - inter + EPSf;
            float iou = inter / uni;
            float cw  = fmaxf(pb.z, tx2) - fminf(pb.x, tx1);
            float chh = fmaxf(pb.w, ty2) - fminf(pb.y, ty1);
            float c2  = cw * cw + chh * chh + EPSf;
            float dx = pb.x + pb.z - tx1 - tx2;
            float dy = pb.y + pb.w - ty1 - ty2;
            float rho2 = (dx * dx + dy * dy) * 0.25f;
            float dat = atanf(w2 / (h2 + EPSf)) - atanf(w1 / (h1 + EPSf));
            float v = (4.f / (float)(CUDART_PI * CUDART_PI)) * dat * dat;
            float alpha = v / (v - iou + 1.f + EPSf);
            aciou = (double)(1.f - (iou - rho2 / c2 - v * alpha));
            // DFL
            const float* base = p + ((size_t)b * CH) * HW + hw;
            float4 lse4 = g_lse[t];
            float lsea[4] = { lse4.x, lse4.y, lse4.z, lse4.w };
            float dd[4] = { fmaxf(cx - tx1, 0.f), fmaxf(cy - ty1, 0.f),
                            fmaxf(tx2 - cx, 0.f), fmaxf(ty2 - cy, 0.f) };
            float sdfl = 0.f;
            #pragma unroll
            for (int s = 0; s < 4; s++) {
                float d = fminf(fmaxf(dd[s] / stride, 0.f), (float)(BINSc - 1) - 1e-6f);
                float lo = floorf(d);
                float a  = d - lo;
                int li = (int)lo;
                float llo = base[(size_t)(s * BINSc + li) * HW];
                float lup = base[(size_t)(s * BINSc + li + 1) * HW];
                sdfl -= (1.f - a) * (llo - lsea[s]) + a * (lup - lsea[s]);
            }
            adfl = (double)sdfl;
            // focal correction at matched label
            float l = lcls;
            float pr = 1.f / (1.f + expf(-l));
            float b0 = focal_base(l);
            float tt = norm;
            float ce = fmaxf(l, 0.f) - l * tt + log1pf(expf(-fabsf(l)));
            float pt = pr * tt + (1.f - pr) * (1.f - tt);
            float at = 0.25f * tt + 0.75f * (1.f - tt);
            acorr = (double)(at * (1.f - pt) * (1.f - pt) * ce - b0);
        }
        double r;
        r = blkReduce256(aciou); if (tid == 0 && r != 0.0) atomicAdd(&g_acc[0], r);
        r = blkReduce256(adfl);  if (tid == 0 && r != 0.0) atomicAdd(&g_acc[1], r);
        r = blkReduce256(acorr); if (tid == 0 && r != 0.0) atomicAdd(&g_acc[2], r);
    } else if (bid < F1_BASE) {
        // ================= focal level 0 (p0) =================
        int start = (bid - F0_BASE) * 256 + tid;
        double v = focal_level<6400>(p0, start, F0_BLOCKS * 256);
        v = blkReduce256(v);
        if (tid == 0 && v != 0.0) atomicAdd(&g_focal, v);
    } else if (bid < F2_BASE) {
        // ================= focal level 1 (p1) =================
        int start = (bid - F1_BASE) * 256 + tid;
        double v = focal_level<1600>(p1, start, F1_BLOCKS * 256);
        v = blkReduce256(v);
        if (tid == 0 && v != 0.0) atomicAdd(&g_focal, v);
    } else {
        // ================= focal level 2 (p2) =================
        int start = (bid - F2_BASE) * 256 + tid;
        double v = focal_level<400>(p2, start, F2_BLOCKS * 256);
        v = blkReduce256(v);
        if (tid == 0 && v != 0.0) atomicAdd(&g_focal, v);
    }

    // ================= shared finisher (last of ALL blocks) =================
    __shared__ int s_last;
    __threadfence();
    if (tid == 0) {
        int pos = atomicAdd(&g_done, 1);
        s_last = (pos == K_BLOCKS - 1);
    }
    __syncthreads();
    if (s_last) {
        __threadfence();
        for (int rr = tid; rr < NROWS; rr += 256) {
            g_ovmax_i[rr] = 0; g_almax_i[rr] = 0;
        }
        if (tid == 0) {
            int cnt = atomicAdd(&g_cnt, 0);
            double den = (double)(cnt > 1 ? cnt : 1);
            out[0] = (float)(7.5 * g_acc[0] / den);
            out[1] = (float)(1.5 * g_acc[1] / den);
            out[2] = (float)(0.5 * (g_acc[2] + g_focal) / den);
            g_acc[0] = 0.0; g_acc[1] = 0.0; g_acc[2] = 0.0;
            g_focal = 0.0; g_cnt = 0; g_done = 0; g_bar = 0; g_predready = 0;
        }
    }
}

// ---------------- launch ----------------
extern "C" void kernel_launch(void* const* d_in, const int* in_sizes, int n_in,
                              void* d_out, int out_size)
{
    const float* p0  = (const float*)d_in[0];
    const float* p1  = (const float*)d_in[1];
    const float* p2  = (const float*)d_in[2];
    const float* gtb = (const float*)d_in[3];
    const int*   gtl = (const int*)d_in[4];
    float* out = (float*)d_out;

    k_all<<<K_BLOCKS, 256>>>(p0, p1, p2, gtb, gtl, out);
}

// round 16
// speedup vs baseline: 1.0227x; 1.0227x over previous
#include <cuda_runtime.h>
#include <cuda_bf16.h>
#include <math.h>
#include <math_constants.h>

#define Bn 16
#define Gn 32
#define Nn 8400
#define NCc 80
#define BINSc 16
#define CH 144          // 4*BINS + NC
#define EPSf 1e-9f
#define MAXFG (Bn * Gn * 10)   // 5120
#define NROWS (Bn * Gn)        // 512

#define PRED_BLOCKS 525        // 525*256 == Bn*Nn exactly
#define ASSIGN_BLOCKS 64       // wave-1 resident (<< 148 SMs)
#define F0_BLOCKS 1170         // level-0 focal (p0)
#define F1_BLOCKS 293          // level-1 focal (p1)
#define F2_BLOCKS 73           // level-2 focal (p2)
#define F0_BASE ASSIGN_BLOCKS                 // 64
#define F1_BASE (F0_BASE + F0_BLOCKS)         // 1234
#define F2_BASE (F1_BASE + F1_BLOCKS)         // 1527
#define K2_BLOCKS (F2_BASE + F2_BLOCKS)       // 1600

// ---------------- scratch (device globals; zero-init at load) ----------------
__device__ float4 g_pred[Bn * Nn];            // pred boxes (x1,y1,x2,y2)
__device__ float4 g_lse[Bn * Nn];             // per-side logsumexp of dfl logits
__device__ unsigned int g_bits[Bn * Nn];      // per-anchor gt bitmask
__device__ int    g_claim[Bn * Nn];           // dedup flag (self-cleaning)
__device__ int    g_topn[NROWS * 10];         // per-row selected anchor indices
__device__ int    g_topcnt[NROWS];
__device__ int    g_ovmax_i[NROWS];           // float-as-int maxima; reset by finisher
__device__ int    g_almax_i[NROWS];
__device__ int    g_fglist[MAXFG];            // t*32 + matched_g
__device__ int    g_cnt;                      // fg count; reset by finisher
__device__ int    g_done;                     // completion counter; reset by finisher
__device__ int    g_bar;                      // grid barrier counter; reset by finisher
__device__ double g_acc[3];                   // ciou, dfl, focal-corr; reset by finisher
__device__ double g_focal;                    // dense focal base; reset by finisher

__constant__ int   c_base[3]   = { 0, 6400, 8000 };
__constant__ int   c_W[3]      = { 80, 40, 20 };
__constant__ float c_stride[3] = { 8.f, 16.f, 32.f };

// ---------------- helpers ----------------
__device__ __forceinline__ void decode_anchor(int n, const float*& p,
    const float* p0, const float* p1, const float* p2,
    int& hw, int& W, int& HW, float& stride)
{
    if (n < 6400)      { p = p0; hw = n;        W = 80; HW = 6400; stride = 8.f;  }
    else if (n < 8000) { p = p1; hw = n - 6400; W = 40; HW = 1600; stride = 16.f; }
    else               { p = p2; hw = n - 8000; W = 20; HW = 400;  stride = 32.f; }
}

__device__ __forceinline__ float iou_fn(float4 pb, float gx1, float gy1,
                                        float gx2, float gy2)
{
    float iw = fmaxf(fminf(gx2, pb.z) - fmaxf(gx1, pb.x), 0.f);
    float ih = fmaxf(fminf(gy2, pb.w) - fmaxf(gy1, pb.y), 0.f);
    float inter = iw * ih;
    float ag = (gx2 - gx1) * (gy2 - gy1);
    float ap = fmaxf(pb.z - pb.x, 0.f) * fmaxf(pb.w - pb.y, 0.f);
    return inter / (ag + ap - inter + EPSf);
}

__device__ __forceinline__ float align_fn(float iou, float l)
{
    float sc = 1.f / (1.f + expf(-l));
    float i2 = iou * iou;
    return sqrtf(sc) * i2 * i2 * i2;
}

__device__ __forceinline__ float focal_base(float l)   // precise (per-anchor path)
{
    float E = expf(l);
    float r = 1.f / (1.f + E);
    float pr = E * r;
    float sp = log1pf(E);
    return 0.75f * pr * pr * sp;
}

__device__ __forceinline__ float focal_base_fast(float l)  // dense-sweep path
{
    // 0.75 * sigmoid(l)^2 * softplus(l), all-MUFU approx path
    float E = __expf(l);                 // logits ~N(0,1): no overflow
    float u = 1.f + E;
    float pr = __fdividef(E, u);         // FMUL + MUFU.RCP
    float l2u = __log2f(u);              // MUFU.LG2
    return (0.75f * 0.6931471805599453f) * pr * pr * l2u;
}

// level-specialized focal sweep: compile-time HW -> constant-divisor index math,
// fp32 per-thread accumulation, one double convert at end
template<int HW>
__device__ __forceinline__ double focal_level(const float* __restrict__ p,
                                              int start, int nthreads)
{
    const int per = NCc * HW / 4;        // compile-time constant
    const int TOT = Bn * per;
    float fsum = 0.f;
    for (int t4 = start; t4 < TOT; t4 += nthreads) {
        int b = t4 / per;                // constant division -> mul/shift
        int r = t4 - b * per;
        const float4* base = (const float4*)(p + ((size_t)b * CH + 4 * BINSc) * HW);
        float4 x = base[r];
        fsum += (focal_base_fast(x.x) + focal_base_fast(x.y)) +
                (focal_base_fast(x.z) + focal_base_fast(x.w));
    }
    return (double)fsum;
}

__device__ __forceinline__ double blkReduce256(double v)
{
    __shared__ double sh[8];
    int lane = threadIdx.x & 31, w = threadIdx.x >> 5;
    #pragma unroll
    for (int o = 16; o; o >>= 1) v += __shfl_down_sync(0xffffffffu, v, o);
    if (lane == 0) sh[w] = v;
    __syncthreads();
    v = (threadIdx.x < 8) ? sh[threadIdx.x] : 0.0;
    if (w == 0) {
        #pragma unroll
        for (int o = 4; o; o >>= 1) v += __shfl_down_sync(0xffu, v, o);
    }
    __syncthreads();
    return v;
}

// software grid barrier among the ASSIGN blocks only (all wave-1 resident)
__device__ __forceinline__ void grid_barrier(int target)
{
    __syncthreads();
    if (threadIdx.x == 0) {
        __threadfence();
        atomicAdd(&g_bar, 1);
        while (atomicAdd(&g_bar, 0) < target) __nanosleep(32);
    }
    __syncthreads();
}

// ---------------- kernel 1: pred/DFL only (R12-proven) ----------------
__global__ void k_pred(const float* __restrict__ p0,
                       const float* __restrict__ p1,
                       const float* __restrict__ p2)
{
    int t = blockIdx.x * blockDim.x + threadIdx.x;   // exactly Bn*Nn threads
    g_bits[t] = 0u;
    int b = t / Nn, n = t % Nn;
    const float* p; int hw, W, HW; float stride;
    decode_anchor(n, p, p0, p1, p2, hw, W, HW, stride);
    const float* base = p + ((size_t)b * CH) * HW + hw;
    float cx = ((hw % W) + 0.5f) * stride;
    float cy = ((hw / W) + 0.5f) * stride;
    float dist[4], lse[4];
    #pragma unroll
    for (int s = 0; s < 4; s++) {
        float l[BINSc], m = -1e30f;
        #pragma unroll
        for (int j = 0; j < BINSc; j++) {
            l[j] = base[(size_t)(s * BINSc + j) * HW];
            m = fmaxf(m, l[j]);
        }
        float sum = 0.f, ws = 0.f;
        #pragma unroll
        for (int j = 0; j < BINSc; j++) {
            float e = expf(l[j] - m);
            sum += e; ws += (float)j * e;
        }
        dist[s] = ws / sum * stride;
        lse[s] = m + logf(sum);
    }
    g_pred[t] = make_float4(cx - dist[0], cy - dist[1], cx + dist[2], cy + dist[3]);
    g_lse[t]  = make_float4(lse[0], lse[1], lse[2], lse[3]);
}

// ---------------- kernel 2: assign (blocks 0..63) + focal (blocks 64+) ----------------
__global__ void __launch_bounds__(256)
k_assign_focal(const float* __restrict__ p0, const float* __restrict__ p1,
               const float* __restrict__ p2,
               const float* __restrict__ gtb, const int* __restrict__ gtl,
               float* __restrict__ out)
{
    const int tid = threadIdx.x;

    if (blockIdx.x < ASSIGN_BLOCKS) {
        const int gtid = blockIdx.x * 256 + tid;

        // ================= phase 1: top-k (warp per row) =================
        {
            const int row = gtid >> 5;            // 0..511 exactly
            const int lane = tid & 31;
            const int b = row >> 5, g = row & 31;
            const float gx1 = gtb[row * 4 + 0], gy1 = gtb[row * 4 + 1];
            const float gx2 = gtb[row * 4 + 2], gy2 = gtb[row * 4 + 3];
            const int lab = gtl[row];
            const float* const pp[3] = { p0, p1, p2 };

            int jx0[3], nx[3], jy0[3], pre[4];
            pre[0] = 0;
            #pragma unroll
            for (int l = 0; l < 3; l++) {
                float s = c_stride[l]; int W = c_W[l];
                int x0 = max(0, (int)floorf(gx1 / s - 0.5f));
                int x1 = min(W - 1, (int)ceilf (gx2 / s - 0.5f));
                int y0 = max(0, (int)floorf(gy1 / s - 0.5f));
                int y1 = min(W - 1, (int)ceilf (gy2 / s - 0.5f));
                jx0[l] = x0; nx[l] = max(0, x1 - x0 + 1);
                jy0[l] = y0; int nyl = max(0, y1 - y0 + 1);
                pre[l + 1] = pre[l] + nx[l] * nyl;
            }
            const int total = pre[3];

            float val[10]; int idx[10];
            #pragma unroll
            for (int k = 0; k < 10; k++) { val[k] = 0.f; idx[k] = 0x7fffffff; }

            for (int c = lane; c < total; c += 32) {
                int l = (c >= pre[1]) + (c >= pre[2]);
                int e = c - pre[l];
                int iy = e / nx[l], ix = e - iy * nx[l];
                int j = jx0[l] + ix, i = jy0[l] + iy;
                float s = c_stride[l];
                float cx = (j + 0.5f) * s;
                float cy = (i + 0.5f) * s;
                if (!(cx > gx1 && cx < gx2 && cy > gy1 && cy < gy2)) continue;
                int W = c_W[l], HW = W * W;
                int hw = i * W + j;
                int n = c_base[l] + hw;
                float4 pb = g_pred[b * Nn + n];
                float iou = iou_fn(pb, gx1, gy1, gx2, gy2);
                float lg = pp[l][((size_t)b * CH + 4 * BINSc + lab) * HW + hw];
                float al = align_fn(iou, lg);
                if (al <= EPSf) continue;
                if (al > val[9] || (al == val[9] && n < idx[9])) {
                    val[9] = al; idx[9] = n;
                    #pragma unroll
                    for (int k = 9; k >= 1; k--) {
                        if (val[k] > val[k - 1] ||
                            (val[k] == val[k - 1] && idx[k] < idx[k - 1])) {
                            float tv = val[k]; val[k] = val[k - 1]; val[k - 1] = tv;
                            int ti = idx[k]; idx[k] = idx[k - 1]; idx[k - 1] = ti;
                        }
                    }
                }
            }

            int cnt = 0;
            for (int it = 0; it < 10; it++) {
                unsigned long long pack =
                    ((unsigned long long)(unsigned)__float_as_int(val[0]) << 32) |
                    (unsigned)(~(unsigned)idx[0]);
                #pragma unroll
                for (int o = 16; o; o >>= 1) {
                    unsigned long long other = __shfl_xor_sync(0xffffffffu, pack, o);
                    if (other > pack) pack = other;
                }
                float wv = __int_as_float((int)(pack >> 32));
                if (wv <= EPSf) break;
                int wn = (int)(~(unsigned)pack);
                if (lane == 0) {
                    g_topn[row * 10 + it] = wn;
                    atomicOr(&g_bits[b * Nn + wn], 1u << g);
                }
                cnt++;
                if (idx[0] == wn) {
                    #pragma unroll
                    for (int k = 0; k < 9; k++) { val[k] = val[k + 1]; idx[k] = idx[k + 1]; }
                    val[9] = 0.f; idx[9] = 0x7fffffff;
                }
            }
            if (lane == 0) g_topcnt[row] = cnt;
        }

        grid_barrier(ASSIGN_BLOCKS);              // g_bar reaches 64

        // ================= phase 2: resolve =================
        if (gtid < NROWS * 10) {
            int row = gtid / 10, slot = gtid % 10;
            if (slot < __ldcg(&g_topcnt[row])) {
                int b = row >> 5;
                int n = __ldcg(&g_topn[row * 10 + slot]);
                int t = b * Nn + n;
                if (!atomicExch(&g_claim[t], 1)) {
                    unsigned int bits = __ldcg(&g_bits[t]);
                    float4 pb = g_pred[t];
                    int mg;
                    if (__popc(bits) > 1) {
                        const float* gbase = gtb + (size_t)b * Gn * 4;
                        float bo = -1.f; int bg = 0;
                        #pragma unroll 8
                        for (int g = 0; g < Gn; g++) {
                            float iou = iou_fn(pb, gbase[g * 4 + 0], gbase[g * 4 + 1],
                                               gbase[g * 4 + 2], gbase[g * 4 + 3]);
                            if (iou > bo) { bo = iou; bg = g; }
                        }
                        mg = bg;
                    } else {
                        mg = __ffs(bits) - 1;
                    }
                    int pos = atomicAdd(&g_cnt, 1);
                    g_fglist[pos] = t * 32 + mg;
                    const float* gb = gtb + ((size_t)(b * Gn + mg)) * 4;
                    int lab = gtl[b * Gn + mg];
                    const float* p; int hw, W, HW; float stride;
                    decode_anchor(n, p, p0, p1, p2, hw, W, HW, stride);
                    float iou = iou_fn(pb, gb[0], gb[1], gb[2], gb[3]);
                    float l = p[((size_t)b * CH + 4 * BINSc + lab) * HW + hw];
                    float al = align_fn(iou, l);
                    atomicMax(&g_ovmax_i[b * Gn + mg], __float_as_int(iou));
                    atomicMax(&g_almax_i[b * Gn + mg], __float_as_int(al));
                }
            }
        }

        grid_barrier(2 * ASSIGN_BLOCKS);          // g_bar reaches 128

        // ================= phase 3: per-fg losses =================
        __shared__ int s_cnt;
        if (tid == 0) s_cnt = atomicAdd(&g_cnt, 0);
        __syncthreads();
        const int cnt = s_cnt;

        double aciou = 0.0, adfl = 0.0, acorr = 0.0;
        if (gtid < cnt) {
            int code = __ldcg(&g_fglist[gtid]);
            int t = code >> 5, mg = code & 31;
            g_claim[t] = 0;                       // self-clean
            int b = t / Nn, n = t % Nn;
            const float* p; int hw, W, HW; float stride;
            decode_anchor(n, p, p0, p1, p2, hw, W, HW, stride);
            float cx = ((hw % W) + 0.5f) * stride;
            float cy = ((hw / W) + 0.5f) * stride;
            const float* gb = gtb + ((size_t)(b * Gn + mg)) * 4;
            float tx1 = gb[0], ty1 = gb[1], tx2 = gb[2], ty2 = gb[3];
            int lab = gtl[b * Gn + mg];
            float4 pb = g_pred[t];
            // norm
            float iou0 = iou_fn(pb, tx1, ty1, tx2, ty2);
            float lcls = p[((size_t)b * CH + 4 * BINSc + lab) * HW + hw];
            float al = align_fn(iou0, lcls);
            float ovmax = __int_as_float(__ldcg(&g_ovmax_i[b * Gn + mg]));
            float almax = __int_as_float(__ldcg(&g_almax_i[b * Gn + mg]));
            float norm = fmaxf(al * ovmax / (almax + EPSf), 0.f);
            // CIoU
            float w1 = pb.z - pb.x, h1 = pb.w - pb.y;
            float w2 = tx2 - tx1,   h2 = ty2 - ty1;
            float iw = fmaxf(fminf(pb.z, tx2) - fmaxf(pb.x, tx1), 0.f);
            float ih = fmaxf(fminf(pb.w, ty2) - fmaxf(pb.y, ty1), 0.f);
            float inter = iw * ih;
            float uni = w1 * h1 + w2 * h2 - inter + EPSf;
            float iou = inter / uni;
            float cw  = fmaxf(pb.z, tx2) - fminf(pb.x, tx1);
            float chh = fmaxf(pb.w, ty2) - fminf(pb.y, ty1);
            float c2  = cw * cw + chh * chh + EPSf;
            float dx = pb.x + pb.z - tx1 - tx2;
            float dy = pb.y + pb.w - ty1 - ty2;
            float rho2 = (dx * dx + dy * dy) * 0.25f;
            float dat = atanf(w2 / (h2 + EPSf)) - atanf(w1 / (h1 + EPSf));
            float v = (4.f / (float)(CUDART_PI * CUDART_PI)) * dat * dat;
            float alpha = v / (v - iou + 1.f + EPSf);
            aciou = (double)(1.f - (iou - rho2 / c2 - v * alpha));
            // DFL
            const float* base = p + ((size_t)b * CH) * HW + hw;
            float4 lse4 = g_lse[t];
            float lsea[4] = { lse4.x, lse4.y, lse4.z, lse4.w };
            float dd[4] = { fmaxf(cx - tx1, 0.f), fmaxf(cy - ty1, 0.f),
                            fmaxf(tx2 - cx, 0.f), fmaxf(ty2 - cy, 0.f) };
            float sdfl = 0.f;
            #pragma unroll
            for (int s = 0; s < 4; s++) {
                float d = fminf(fmaxf(dd[s] / stride, 0.f), (float)(BINSc - 1) - 1e-6f);
                float lo = floorf(d);
                float a  = d - lo;
                int li = (int)lo;
                float llo = base[(size_t)(s * BINSc + li) * HW];
                float lup = base[(size_t)(s * BINSc + li + 1) * HW];
                sdfl -= (1.f - a) * (llo - lsea[s]) + a * (lup - lsea[s]);
            }
            adfl = (double)sdfl;
            // focal correction at matched label
            float l = lcls;
            float pr = 1.f / (1.f + expf(-l));
            float b0 = focal_base(l);
            float tt = norm;
            float ce = fmaxf(l, 0.f) - l * tt + log1pf(expf(-fabsf(l)));
            float pt = pr * tt + (1.f - pr) * (1.f - tt);
            float at = 0.25f * tt + 0.75f * (1.f - tt);
            acorr = (double)(at * (1.f - pt) * (1.f - pt) * ce - b0);
        }
        double r;
        r = blkReduce256(aciou); if (tid == 0 && r != 0.0) atomicAdd(&g_acc[0], r);
        r = blkReduce256(adfl);  if (tid == 0 && r != 0.0) atomicAdd(&g_acc[1], r);
        r = blkReduce256(acorr); if (tid == 0 && r != 0.0) atomicAdd(&g_acc[2], r);
    } else if (blockIdx.x < F1_BASE) {
        // ================= focal level 0 (p0) =================
        int start = (blockIdx.x - F0_BASE) * 256 + tid;
        double v = focal_level<6400>(p0, start, F0_BLOCKS * 256);
        v = blkReduce256(v);
        if (tid == 0 && v != 0.0) atomicAdd(&g_focal, v);
    } else if (blockIdx.x < F2_BASE) {
        // ================= focal level 1 (p1) =================
        int start = (blockIdx.x - F1_BASE) * 256 + tid;
        double v = focal_level<1600>(p1, start, F1_BLOCKS * 256);
        v = blkReduce256(v);
        if (tid == 0 && v != 0.0) atomicAdd(&g_focal, v);
    } else {
        // ================= focal level 2 (p2) =================
        int start = (blockIdx.x - F2_BASE) * 256 + tid;
        double v = focal_level<400>(p2, start, F2_BLOCKS * 256);
        v = blkReduce256(v);
        if (tid == 0 && v != 0.0) atomicAdd(&g_focal, v);
    }

    // ================= shared finisher (last of ALL K2 blocks) =================
    __shared__ int s_last;
    __threadfence();
    if (tid == 0) {
        int pos = atomicAdd(&g_done, 1);
        s_last = (pos == K2_BLOCKS - 1);
    }
    __syncthreads();
    if (s_last) {
        __threadfence();
        for (int rr = tid; rr < NROWS; rr += 256) {
            g_ovmax_i[rr] = 0; g_almax_i[rr] = 0;
        }
        if (tid == 0) {
            int cnt = atomicAdd(&g_cnt, 0);
            double den = (double)(cnt > 1 ? cnt : 1);
            out[0] = (float)(7.5 * g_acc[0] / den);
            out[1] = (float)(1.5 * g_acc[1] / den);
            out[2] = (float)(0.5 * (g_acc[2] + g_focal) / den);
            g_acc[0] = 0.0; g_acc[1] = 0.0; g_acc[2] = 0.0;
            g_focal = 0.0; g_cnt = 0; g_done = 0; g_bar = 0;
        }
    }
}

// ---------------- launch ----------------
extern "C" void kernel_launch(void* const* d_in, const int* in_sizes, int n_in,
                              void* d_out, int out_size)
{
    const float* p0  = (const float*)d_in[0];
    const float* p1  = (const float*)d_in[1];
    const float* p2  = (const float*)d_in[2];
    const float* gtb = (const float*)d_in[3];
    const int*   gtl = (const int*)d_in[4];
    float* out = (float*)d_out;

    k_pred<<<PRED_BLOCKS, 256>>>(p0, p1, p2);
    k_assign_focal<<<K2_BLOCKS, 256>>>(p0, p1, p2, gtb, gtl, out);
}

// round 17
// speedup vs baseline: 1.2079x; 1.1810x over previous
#include <cuda_runtime.h>
#include <cuda_bf16.h>
#include <math.h>
#include <math_constants.h>

#define Bn 16
#define Gn 32
#define Nn 8400
#define NCc 80
#define BINSc 16
#define CH 144          // 4*BINS + NC
#define EPSf 1e-9f
#define MAXFG (Bn * Gn * 10)   // 5120
#define NROWS (Bn * Gn)        // 512

#define PRED_BLOCKS 525        // 525*256 == Bn*Nn exactly
#define ASSIGN_BLOCKS 128      // 2 warps per row; wave-1 resident (< 148 SMs)
#define F0_BLOCKS 1170         // level-0 focal (p0)
#define F1_BLOCKS 293          // level-1 focal (p1)
#define F2_BLOCKS 73           // level-2 focal (p2)
#define F0_BASE ASSIGN_BLOCKS                 // 128
#define F1_BASE (F0_BASE + F0_BLOCKS)         // 1298
#define F2_BASE (F1_BASE + F1_BLOCKS)         // 1591
#define K2_BLOCKS (F2_BASE + F2_BLOCKS)       // 1664

#define PACK_EMPTY 0x80000000ull   // val=0.f, idx=0x7fffffff

// ---------------- scratch (device globals; zero-init at load) ----------------
__device__ float4 g_pred[Bn * Nn];            // pred boxes (x1,y1,x2,y2)
__device__ float4 g_lse[Bn * Nn];             // per-side logsumexp of dfl logits
__device__ unsigned int g_bits[Bn * Nn];      // per-anchor gt bitmask
__device__ int    g_claim[Bn * Nn];           // dedup flag (self-cleaning)
__device__ int    g_topn[NROWS * 10];         // per-row selected anchor indices
__device__ int    g_topcnt[NROWS];
__device__ int    g_ovmax_i[NROWS];           // float-as-int maxima; reset by finisher
__device__ int    g_almax_i[NROWS];
__device__ int    g_fglist[MAXFG];            // t*32 + matched_g
__device__ int    g_cnt;                      // fg count; reset by finisher
__device__ int    g_done;                     // completion counter; reset by finisher
__device__ int    g_bar;                      // grid barrier counter; reset by finisher
__device__ double g_acc[3];                   // ciou, dfl, focal-corr; reset by finisher
__device__ double g_focal;                    // dense focal base; reset by finisher

__constant__ int   c_base[3]   = { 0, 6400, 8000 };
__constant__ int   c_W[3]      = { 80, 40, 20 };
__constant__ float c_stride[3] = { 8.f, 16.f, 32.f };

// ---------------- helpers ----------------
__device__ __forceinline__ void decode_anchor(int n, const float*& p,
    const float* p0, const float* p1, const float* p2,
    int& hw, int& W, int& HW, float& stride)
{
    if (n < 6400)      { p = p0; hw = n;        W = 80; HW = 6400; stride = 8.f;  }
    else if (n < 8000) { p = p1; hw = n - 6400; W = 40; HW = 1600; stride = 16.f; }
    else               { p = p2; hw = n - 8000; W = 20; HW = 400;  stride = 32.f; }
}

__device__ __forceinline__ float iou_fn(float4 pb, float gx1, float gy1,
                                        float gx2, float gy2)
{
    float iw = fmaxf(fminf(gx2, pb.z) - fmaxf(gx1, pb.x), 0.f);
    float ih = fmaxf(fminf(gy2, pb.w) - fmaxf(gy1, pb.y), 0.f);
    float inter = iw * ih;
    float ag = (gx2 - gx1) * (gy2 - gy1);
    float ap = fmaxf(pb.z - pb.x, 0.f) * fmaxf(pb.w - pb.y, 0.f);
    return inter / (ag + ap - inter + EPSf);
}

__device__ __forceinline__ float align_fn(float iou, float l)
{
    float sc = 1.f / (1.f + expf(-l));
    float i2 = iou * iou;
    return sqrtf(sc) * i2 * i2 * i2;
}

__device__ __forceinline__ float focal_base(float l)   // precise (per-anchor path)
{
    float E = expf(l);
    float r = 1.f / (1.f + E);
    float pr = E * r;
    float sp = log1pf(E);
    return 0.75f * pr * pr * sp;
}

__device__ __forceinline__ float focal_base_fast(float l)  // dense-sweep path
{
    float E = __expf(l);                 // logits ~N(0,1): no overflow
    float u = 1.f + E;
    float pr = __fdividef(E, u);         // FMUL + MUFU.RCP
    float l2u = __log2f(u);              // MUFU.LG2
    return (0.75f * 0.6931471805599453f) * pr * pr * l2u;
}

__device__ __forceinline__ float focal4(float4 x)
{
    return (focal_base_fast(x.x) + focal_base_fast(x.y)) +
           (focal_base_fast(x.z) + focal_base_fast(x.w));
}

// level-specialized focal sweep with 4-way batched loads (MLP=4)
template<int HW>
__device__ __forceinline__ double focal_level(const float* __restrict__ p,
                                              int start, int nthreads)
{
    const int per = NCc * HW / 4;        // compile-time constant
    const int TOT = Bn * per;
    float fsum = 0.f;
    int t4 = start;
    for (; t4 + 3 * nthreads < TOT; t4 += 4 * nthreads) {
        int a0 = t4, a1 = t4 + nthreads, a2 = t4 + 2 * nthreads, a3 = t4 + 3 * nthreads;
        int b0 = a0 / per, b1 = a1 / per, b2 = a2 / per, b3 = a3 / per;
        float4 x0 = ((const float4*)(p + ((size_t)b0 * CH + 4 * BINSc) * HW))[a0 - b0 * per];
        float4 x1 = ((const float4*)(p + ((size_t)b1 * CH + 4 * BINSc) * HW))[a1 - b1 * per];
        float4 x2 = ((const float4*)(p + ((size_t)b2 * CH + 4 * BINSc) * HW))[a2 - b2 * per];
        float4 x3 = ((const float4*)(p + ((size_t)b3 * CH + 4 * BINSc) * HW))[a3 - b3 * per];
        fsum += focal4(x0) + focal4(x1) + focal4(x2) + focal4(x3);
    }
    for (; t4 < TOT; t4 += nthreads) {
        int b = t4 / per;
        float4 x = ((const float4*)(p + ((size_t)b * CH + 4 * BINSc) * HW))[t4 - b * per];
        fsum += focal4(x);
    }
    return (double)fsum;
}

__device__ __forceinline__ double blkReduce256(double v)
{
    __shared__ double sh[8];
    int lane = threadIdx.x & 31, w = threadIdx.x >> 5;
    #pragma unroll
    for (int o = 16; o; o >>= 1) v += __shfl_down_sync(0xffffffffu, v, o);
    if (lane == 0) sh[w] = v;
    __syncthreads();
    v = (threadIdx.x < 8) ? sh[threadIdx.x] : 0.0;
    if (w == 0) {
        #pragma unroll
        for (int o = 4; o; o >>= 1) v += __shfl_down_sync(0xffu, v, o);
    }
    __syncthreads();
    return v;
}

// software grid barrier among the ASSIGN blocks only (all wave-1 resident)
__device__ __forceinline__ void grid_barrier(int target)
{
    __syncthreads();
    if (threadIdx.x == 0) {
        __threadfence();
        atomicAdd(&g_bar, 1);
        while (atomicAdd(&g_bar, 0) < target) __nanosleep(32);
    }
    __syncthreads();
}

// ---------------- kernel 1: pred/DFL only (R12-proven) ----------------
__global__ void k_pred(const float* __restrict__ p0,
                       const float* __restrict__ p1,
                       const float* __restrict__ p2)
{
    int t = blockIdx.x * blockDim.x + threadIdx.x;   // exactly Bn*Nn threads
    g_bits[t] = 0u;
    int b = t / Nn, n = t % Nn;
    const float* p; int hw, W, HW; float stride;
    decode_anchor(n, p, p0, p1, p2, hw, W, HW, stride);
    const float* base = p + ((size_t)b * CH) * HW + hw;
    float cx = ((hw % W) + 0.5f) * stride;
    float cy = ((hw / W) + 0.5f) * stride;
    float dist[4], lse[4];
    #pragma unroll
    for (int s = 0; s < 4; s++) {
        float l[BINSc], m = -1e30f;
        #pragma unroll
        for (int j = 0; j < BINSc; j++) {
            l[j] = base[(size_t)(s * BINSc + j) * HW];
            m = fmaxf(m, l[j]);
        }
        float sum = 0.f, ws = 0.f;
        #pragma unroll
        for (int j = 0; j < BINSc; j++) {
            float e = expf(l[j] - m);
            sum += e; ws += (float)j * e;
        }
        dist[s] = ws / sum * stride;
        lse[s] = m + logf(sum);
    }
    g_pred[t] = make_float4(cx - dist[0], cy - dist[1], cx + dist[2], cy + dist[3]);
    g_lse[t]  = make_float4(lse[0], lse[1], lse[2], lse[3]);
}

// ---------------- kernel 2: assign (blocks 0..127, 2 warps/row) + focal ----------------
__global__ void __launch_bounds__(256)
k_assign_focal(const float* __restrict__ p0, const float* __restrict__ p1,
               const float* __restrict__ p2,
               const float* __restrict__ gtb, const int* __restrict__ gtl,
               float* __restrict__ out)
{
    const int tid = threadIdx.x;

    if (blockIdx.x < ASSIGN_BLOCKS) {
        const int gtid = blockIdx.x * 256 + tid;
        __shared__ unsigned long long sh_top[8][10];

        // ===== phase 1: top-k, TWO warps per row =====
        {
            const int wid = tid >> 5;
            const int lane = tid & 31;
            const int w = blockIdx.x * 8 + wid;   // 0..1023
            const int row = w >> 1;               // 0..511
            const int half = w & 1;
            const int b = row >> 5, g = row & 31;
            const float gx1 = gtb[row * 4 + 0], gy1 = gtb[row * 4 + 1];
            const float gx2 = gtb[row * 4 + 2], gy2 = gtb[row * 4 + 3];
            const int lab = gtl[row];
            const float* const pp[3] = { p0, p1, p2 };

            int jx0[3], nx[3], jy0[3], pre[4];
            pre[0] = 0;
            #pragma unroll
            for (int l = 0; l < 3; l++) {
                float s = c_stride[l]; int W = c_W[l];
                int x0 = max(0, (int)floorf(gx1 / s - 0.5f));
                int x1 = min(W - 1, (int)ceilf (gx2 / s - 0.5f));
                int y0 = max(0, (int)floorf(gy1 / s - 0.5f));
                int y1 = min(W - 1, (int)ceilf (gy2 / s - 0.5f));
                jx0[l] = x0; nx[l] = max(0, x1 - x0 + 1);
                jy0[l] = y0; int nyl = max(0, y1 - y0 + 1);
                pre[l + 1] = pre[l] + nx[l] * nyl;
            }
            const int total = pre[3];

            float val[10]; int idx[10];
            #pragma unroll
            for (int k = 0; k < 10; k++) { val[k] = 0.f; idx[k] = 0x7fffffff; }

            // disjoint halves: c = half*32+lane, stride 64
            for (int c = half * 32 + lane; c < total; c += 64) {
                int l = (c >= pre[1]) + (c >= pre[2]);
                int e = c - pre[l];
                int iy = e / nx[l], ix = e - iy * nx[l];
                int j = jx0[l] + ix, i = jy0[l] + iy;
                float s = c_stride[l];
                float cx = (j + 0.5f) * s;
                float cy = (i + 0.5f) * s;
                if (!(cx > gx1 && cx < gx2 && cy > gy1 && cy < gy2)) continue;
                int W = c_W[l], HW = W * W;
                int hw = i * W + j;
                int n = c_base[l] + hw;
                float4 pb = g_pred[b * Nn + n];
                float iou = iou_fn(pb, gx1, gy1, gx2, gy2);
                float lg = pp[l][((size_t)b * CH + 4 * BINSc + lab) * HW + hw];
                float al = align_fn(iou, lg);
                if (al <= EPSf) continue;
                if (al > val[9] || (al == val[9] && n < idx[9])) {
                    val[9] = al; idx[9] = n;
                    #pragma unroll
                    for (int k = 9; k >= 1; k--) {
                        if (val[k] > val[k - 1] ||
                            (val[k] == val[k - 1] && idx[k] < idx[k - 1])) {
                            float tv = val[k]; val[k] = val[k - 1]; val[k - 1] = tv;
                            int ti = idx[k]; idx[k] = idx[k - 1]; idx[k - 1] = ti;
                        }
                    }
                }
            }

            // per-warp lane merge: 10 rounds, publish sorted warp top-10 to shared
            for (int it = 0; it < 10; it++) {
                unsigned long long pack =
                    ((unsigned long long)(unsigned)__float_as_int(val[0]) << 32) |
                    (unsigned)(~(unsigned)idx[0]);
                unsigned long long m = pack;
                #pragma unroll
                for (int o = 16; o; o >>= 1) {
                    unsigned long long other = __shfl_xor_sync(0xffffffffu, m, o);
                    if (other > m) m = other;
                }
                if (lane == 0) sh_top[wid][it] = m;
                int wn = (int)(~(unsigned)m);
                if (idx[0] == wn) {               // pop my head (empties pop harmlessly)
                    #pragma unroll
                    for (int k = 0; k < 9; k++) { val[k] = val[k + 1]; idx[k] = idx[k + 1]; }
                    val[9] = 0.f; idx[9] = 0x7fffffff;
                }
            }
            __syncthreads();

            // even warp of each pair merges the two disjoint sorted 10-lists
            if (half == 0) {
                unsigned long long pk;
                if (lane < 10)      pk = sh_top[wid][lane];
                else if (lane < 20) pk = sh_top[wid + 1][lane - 10];
                else                pk = PACK_EMPTY;
                int cnt = 0;
                for (int it = 0; it < 10; it++) {
                    unsigned long long m = pk;
                    #pragma unroll
                    for (int o = 16; o; o >>= 1) {
                        unsigned long long other = __shfl_xor_sync(0xffffffffu, m, o);
                        if (other > m) m = other;
                    }
                    float wv = __int_as_float((int)(m >> 32));
                    if (wv <= EPSf) break;
                    int wn = (int)(~(unsigned)m);
                    if (lane == 0) {
                        g_topn[row * 10 + it] = wn;
                        atomicOr(&g_bits[b * Nn + wn], 1u << g);
                    }
                    cnt++;
                    if (pk == m) pk = PACK_EMPTY; // indices disjoint -> unique pop
                }
                if (lane == 0) g_topcnt[row] = cnt;
            }
        }

        grid_barrier(ASSIGN_BLOCKS);              // g_bar reaches 128

        // ===== phase 2: resolve =====
        if (gtid < NROWS * 10) {
            int row = gtid / 10, slot = gtid % 10;
            if (slot < __ldcg(&g_topcnt[row])) {
                int b = row >> 5;
                int n = __ldcg(&g_topn[row * 10 + slot]);
                int t = b * Nn + n;
                if (!atomicExch(&g_claim[t], 1)) {
                    unsigned int bits = __ldcg(&g_bits[t]);
                    float4 pb = g_pred[t];
                    int mg;
                    if (__popc(bits) > 1) {
                        const float* gbase = gtb + (size_t)b * Gn * 4;
                        float bo = -1.f; int bg = 0;
                        #pragma unroll 8
                        for (int g = 0; g < Gn; g++) {
                            float iou = iou_fn(pb, gbase[g * 4 + 0], gbase[g * 4 + 1],
                                               gbase[g * 4 + 2], gbase[g * 4 + 3]);
                            if (iou > bo) { bo = iou; bg = g; }
                        }
                        mg = bg;
                    } else {
                        mg = __ffs(bits) - 1;
                    }
                    int pos = atomicAdd(&g_cnt, 1);
                    g_fglist[pos] = t * 32 + mg;
                    const float* gb = gtb + ((size_t)(b * Gn + mg)) * 4;
                    int lab = gtl[b * Gn + mg];
                    const float* p; int hw, W, HW; float stride;
                    decode_anchor(n, p, p0, p1, p2, hw, W, HW, stride);
                    float iou = iou_fn(pb, gb[0], gb[1], gb[2], gb[3]);
                    float l = p[((size_t)b * CH + 4 * BINSc + lab) * HW + hw];
                    float al = align_fn(iou, l);
                    atomicMax(&g_ovmax_i[b * Gn + mg], __float_as_int(iou));
                    atomicMax(&g_almax_i[b * Gn + mg], __float_as_int(al));
                }
            }
        }

        grid_barrier(2 * ASSIGN_BLOCKS);          // g_bar reaches 256

        // ===== phase 3: per-fg losses =====
        __shared__ int s_cnt;
        if (tid == 0) s_cnt = atomicAdd(&g_cnt, 0);
        __syncthreads();
        const int cnt = s_cnt;

        double aciou = 0.0, adfl = 0.0, acorr = 0.0;
        if (gtid < cnt) {
            int code = __ldcg(&g_fglist[gtid]);
            int t = code >> 5, mg = code & 31;
            g_claim[t] = 0;                       // self-clean
            int b = t / Nn, n = t % Nn;
            const float* p; int hw, W, HW; float stride;
            decode_anchor(n, p, p0, p1, p2, hw, W, HW, stride);
            float cx = ((hw % W) + 0.5f) * stride;
            float cy = ((hw / W) + 0.5f) * stride;
            const float* gb = gtb + ((size_t)(b * Gn + mg)) * 4;
            float tx1 = gb[0], ty1 = gb[1], tx2 = gb[2], ty2 = gb[3];
            int lab = gtl[b * Gn + mg];
            float4 pb = g_pred[t];
            // norm
            float iou0 = iou_fn(pb, tx1, ty1, tx2, ty2);
            float lcls = p[((size_t)b * CH + 4 * BINSc + lab) * HW + hw];
            float al = align_fn(iou0, lcls);
            float ovmax = __int_as_float(__ldcg(&g_ovmax_i[b * Gn + mg]));
            float almax = __int_as_float(__ldcg(&g_almax_i[b * Gn + mg]));
            float norm = fmaxf(al * ovmax / (almax + EPSf), 0.f);
            // CIoU
            float w1 = pb.z - pb.x, h1 = pb.w - pb.y;
            float w2 = tx2 - tx1,   h2 = ty2 - ty1;
            float iw = fmaxf(fminf(pb.z, tx2) - fmaxf(pb.x, tx1), 0.f);
            float ih = fmaxf(fminf(pb.w, ty2) - fmaxf(pb.y, ty1), 0.f);
            float inter = iw * ih;
            float uni = w1 * h1 + w2 * h2 - inter + EPSf;
            float iou = inter / uni;
            float cw  = fmaxf(pb.z, tx2) - fminf(pb.x, tx1);
            float chh = fmaxf(pb.w, ty2) - fminf(pb.y, ty1);
            float c2  = cw * cw + chh * chh + EPSf;
            float dx = pb.x + pb.z - tx1 - tx2;
            float dy = pb.y + pb.w - ty1 - ty2;
            float rho2 = (dx * dx + dy * dy) * 0.25f;
            float dat = atanf(w2 / (h2 + EPSf)) - atanf(w1 / (h1 + EPSf));
            float v = (4.f / (float)(CUDART_PI * CUDART_PI)) * dat * dat;
            float alpha = v / (v - iou + 1.f + EPSf);
            aciou = (double)(1.f - (iou - rho2 / c2 - v * alpha));
            // DFL
            const float* base = p + ((size_t)b * CH) * HW + hw;
            float4 lse4 = g_lse[t];
            float lsea[4] = { lse4.x, lse4.y, lse4.z, lse4.w };
            float dd[4] = { fmaxf(cx - tx1, 0.f), fmaxf(cy - ty1, 0.f),
                            fmaxf(tx2 - cx, 0.f), fmaxf(ty2 - cy, 0.f) };
            float sdfl = 0.f;
            #pragma unroll
            for (int s = 0; s < 4; s++) {
                float d = fminf(fmaxf(dd[s] / stride, 0.f), (float)(BINSc - 1) - 1e-6f);
                float lo = floorf(d);
                float a  = d - lo;
                int li = (int)lo;
                float llo = base[(size_t)(s * BINSc + li) * HW];
                float lup = base[(size_t)(s * BINSc + li + 1) * HW];
                sdfl -= (1.f - a) * (llo - lsea[s]) + a * (lup - lsea[s]);
            }
            adfl = (double)sdfl;
            // focal correction at matched label
            float l = lcls;
            float pr = 1.f / (1.f + expf(-l));
            float b0 = focal_base(l);
            float tt = norm;
            float ce = fmaxf(l, 0.f) - l * tt + log1pf(expf(-fabsf(l)));
            float pt = pr * tt + (1.f - pr) * (1.f - tt);
            float at = 0.25f * tt + 0.75f * (1.f - tt);
            acorr = (double)(at * (1.f - pt) * (1.f - pt) * ce - b0);
        }
        double r;
        r = blkReduce256(aciou); if (tid == 0 && r != 0.0) atomicAdd(&g_acc[0], r);
        r = blkReduce256(adfl);  if (tid == 0 && r != 0.0) atomicAdd(&g_acc[1], r);
        r = blkReduce256(acorr); if (tid == 0 && r != 0.0) atomicAdd(&g_acc[2], r);
    } else if (blockIdx.x < F1_BASE) {
        int start = (blockIdx.x - F0_BASE) * 256 + tid;
        double v = focal_level<6400>(p0, start, F0_BLOCKS * 256);
        v = blkReduce256(v);
        if (tid == 0 && v != 0.0) atomicAdd(&g_focal, v);
    } else if (blockIdx.x < F2_BASE) {
        int start = (blockIdx.x - F1_BASE) * 256 + tid;
        double v = focal_level<1600>(p1, start, F1_BLOCKS * 256);
        v = blkReduce256(v);
        if (tid == 0 && v != 0.0) atomicAdd(&g_focal, v);
    } else {
        int start = (blockIdx.x - F2_BASE) * 256 + tid;
        double v = focal_level<400>(p2, start, F2_BLOCKS * 256);
        v = blkReduce256(v);
        if (tid == 0 && v != 0.0) atomicAdd(&g_focal, v);
    }

    // ===== shared finisher (last of ALL K2 blocks) =====
    __shared__ int s_last;
    __threadfence();
    if (tid == 0) {
        int pos = atomicAdd(&g_done, 1);
        s_last = (pos == K2_BLOCKS - 1);
    }
    __syncthreads();
    if (s_last) {
        __threadfence();
        for (int rr = tid; rr < NROWS; rr += 256) {
            g_ovmax_i[rr] = 0; g_almax_i[rr] = 0;
        }
        if (tid == 0) {
            int cnt = atomicAdd(&g_cnt, 0);
            double den = (double)(cnt > 1 ? cnt : 1);
            out[0] = (float)(7.5 * g_acc[0] / den);
            out[1] = (float)(1.5 * g_acc[1] / den);
            out[2] = (float)(0.5 * (g_acc[2] + g_focal) / den);
            g_acc[0] = 0.0; g_acc[1] = 0.0; g_acc[2] = 0.0;
            g_focal = 0.0; g_cnt = 0; g_done = 0; g_bar = 0;
        }
    }
}

// ---------------- launch ----------------
extern "C" void kernel_launch(void* const* d_in, const int* in_sizes, int n_in,
                              void* d_out, int out_size)
{
    const float* p0  = (const float*)d_in[0];
    const float* p1  = (const float*)d_in[1];
    const float* p2  = (const float*)d_in[2];
    const float* gtb = (const float*)d_in[3];
    const int*   gtl = (const int*)d_in[4];
    float* out = (float*)d_out;

    k_pred<<<PRED_BLOCKS, 256>>>(p0, p1, p2);
    k_assign_focal<<<K2_BLOCKS, 256>>>(p0, p1, p2, gtb, gtl, out);
}